// round 1
// baseline (speedup 1.0000x reference)
#include <cuda_runtime.h>

#define T   512
#define K   4
#define G   20000
#define EPG 3
#define B   512

#define BTILE 8     // batches per block in the gather kernel
#define BLK   256   // threads per block (gather kernel)
#define GPB   2048  // g's per block -> 8 iterations of 256

// h2 scratch: [B][T] float4 (k-vector) = 4 MB, stays L2-resident.
__device__ float4 g_h2[B * T];

__device__ __forceinline__ float leaky(float x) {
    return x > 0.0f ? x : 0.01f * x;
}

// ---------------------------------------------------------------------------
// Kernel A: h2[b,t,:] = leaky( leaky(f[b,t]*w1[t,:] + b1[t,:]) @ w2[t,:,:] + b2[t,:] )
// Grid: B blocks x T threads. ~20 FMA/thread; bandwidth-trivial.
// ---------------------------------------------------------------------------
__global__ void h2_kernel(const float*  __restrict__ features,
                          const float4* __restrict__ w1,
                          const float4* __restrict__ b1,
                          const float4* __restrict__ w2,
                          const float4* __restrict__ b2) {
    const int t = threadIdx.x;
    const int b = blockIdx.x;

    const float f   = features[b * T + t];
    const float4 w1v = w1[t];
    const float4 b1v = b1[t];
    const float4 b2v = b2[t];

    const float h0 = leaky(fmaf(f, w1v.x, b1v.x));
    const float h1 = leaky(fmaf(f, w1v.y, b1v.y));
    const float h2 = leaky(fmaf(f, w1v.z, b1v.z));
    const float h3 = leaky(fmaf(f, w1v.w, b1v.w));

    // w2[t, j, k]: row j is a float4 over k
    const float4 w20 = w2[t * 4 + 0];
    const float4 w21 = w2[t * 4 + 1];
    const float4 w22 = w2[t * 4 + 2];
    const float4 w23 = w2[t * 4 + 3];

    float4 o;
    o.x = leaky(fmaf(h3, w23.x, fmaf(h2, w22.x, fmaf(h1, w21.x, fmaf(h0, w20.x, b2v.x)))));
    o.y = leaky(fmaf(h3, w23.y, fmaf(h2, w22.y, fmaf(h1, w21.y, fmaf(h0, w20.y, b2v.y)))));
    o.z = leaky(fmaf(h3, w23.z, fmaf(h2, w22.z, fmaf(h1, w21.z, fmaf(h0, w20.z, b2v.z)))));
    o.w = leaky(fmaf(h3, w23.w, fmaf(h2, w22.w, fmaf(h1, w21.w, fmaf(h0, w20.w, b2v.w)))));

    g_h2[b * T + t] = o;
}

// ---------------------------------------------------------------------------
// Kernel B: out[b,g] = sum_e dot(h2[b, edge[g,e], :], w3[g,e,:]) + b3[g]
// Block: BTILE batches of h2 staged in SMEM (BTILE*T float4 = 64 KB).
// Each thread owns one g per iteration; w3/edge loads amortized over BTILE b's.
// ---------------------------------------------------------------------------
__global__ void gather_kernel(const int*   __restrict__ edge,
                              const float* __restrict__ w3,
                              const float* __restrict__ b3,
                              float*       __restrict__ out) {
    extern __shared__ float4 s_h2[];   // [BTILE * T]

    const int b0 = blockIdx.y * BTILE;

    // Stage BTILE batches of h2 into shared memory (coalesced float4).
    const float4* src = g_h2 + (size_t)b0 * T;
    #pragma unroll
    for (int i = threadIdx.x; i < BTILE * T; i += BLK) {
        s_h2[i] = src[i];
    }
    __syncthreads();

    const int gbase = blockIdx.x * GPB + threadIdx.x;

    #pragma unroll
    for (int it = 0; it < GPB / BLK; it++) {
        const int g = gbase + it * BLK;
        if (g >= G) break;

        const int e0 = edge[g * 3 + 0];
        const int e1 = edge[g * 3 + 1];
        const int e2 = edge[g * 3 + 2];

        // w3[g] = 12 contiguous floats, 16B-aligned (g*48 bytes)
        const float4* w3p = reinterpret_cast<const float4*>(w3 + (size_t)g * 12);
        const float4 wa = w3p[0];
        const float4 wb = w3p[1];
        const float4 wc = w3p[2];
        const float bias = b3[g];

        float acc[BTILE];
        #pragma unroll
        for (int b = 0; b < BTILE; b++) {
            const float4 va = s_h2[b * T + e0];
            const float4 vb = s_h2[b * T + e1];
            const float4 vc = s_h2[b * T + e2];
            float r = bias;
            r = fmaf(va.x, wa.x, r); r = fmaf(va.y, wa.y, r);
            r = fmaf(va.z, wa.z, r); r = fmaf(va.w, wa.w, r);
            r = fmaf(vb.x, wb.x, r); r = fmaf(vb.y, wb.y, r);
            r = fmaf(vb.z, wb.z, r); r = fmaf(vb.w, wb.w, r);
            r = fmaf(vc.x, wc.x, r); r = fmaf(vc.y, wc.y, r);
            r = fmaf(vc.z, wc.z, r); r = fmaf(vc.w, wc.w, r);
            acc[b] = r;
        }

        #pragma unroll
        for (int b = 0; b < BTILE; b++) {
            out[(size_t)(b0 + b) * G + g] = acc[b];
        }
    }
}

extern "C" void kernel_launch(void* const* d_in, const int* in_sizes, int n_in,
                              void* d_out, int out_size) {
    const float* features = (const float*)d_in[0];   // [B, T]
    const float* w1       = (const float*)d_in[1];   // [T, K]
    const float* b1       = (const float*)d_in[2];   // [T, K]
    const float* w2       = (const float*)d_in[3];   // [T, K, K]
    const float* b2       = (const float*)d_in[4];   // [T, K]
    const float* w3       = (const float*)d_in[5];   // [G, EPG, K]
    const float* b3       = (const float*)d_in[6];   // [G]
    const int*   edge     = (const int*)  d_in[7];   // [G, EPG]
    float*       out      = (float*)d_out;           // [B, G]

    h2_kernel<<<B, T>>>(features,
                        (const float4*)w1, (const float4*)b1,
                        (const float4*)w2, (const float4*)b2);

    const int smem = BTILE * T * sizeof(float4);     // 64 KB
    cudaFuncSetAttribute(gather_kernel,
                         cudaFuncAttributeMaxDynamicSharedMemorySize, smem);
    dim3 grid((G + GPB - 1) / GPB, B / BTILE);
    gather_kernel<<<grid, BLK, smem>>>(edge, w3, b3, out);
}

// round 2
// speedup vs baseline: 1.0379x; 1.0379x over previous
#include <cuda_runtime.h>
#include <cuda_fp16.h>

#define T   512
#define K   4
#define G   20000
#define EPG 3
#define B   512

#define BT     32                 // batches per tile (= lanes per warp)
#define NBT    (B / BT)           // 16 b-tiles
#define NWARP  17                 // warps per gather block
#define GPB    (NWARP * 32)       // 544 g per block
#define NGB    37                 // g-blocks: 37*544 = 20128 >= 20000; grid = 16*37 = 592 = 4.0 waves

// h2 in fp16, transposed layout: [bt][t][k_pair][b_in]  (half2 elements)
// size = 16 * 512 * 2 * 32 half2 = 2 MB
__device__ __half2 g_h2h[NBT * T * 2 * BT];

__device__ __forceinline__ float leaky(float x) {
    return x > 0.0f ? x : 0.01f * x;
}

// ---------------------------------------------------------------------------
// Kernel A: compute h2 and store as fp16 in the transposed [bt][t][kp][b] layout.
// block = (32 b_in, 16 t_local); grid = (16 bt, 32 t_chunks). Coalesced stores.
// ---------------------------------------------------------------------------
__global__ void h2_kernel(const float*  __restrict__ features,
                          const float4* __restrict__ w1,
                          const float4* __restrict__ b1,
                          const float4* __restrict__ w2,
                          const float4* __restrict__ b2) {
    const int b_in = threadIdx.x;
    const int t    = blockIdx.y * 16 + threadIdx.y;
    const int bt   = blockIdx.x;
    const int b    = bt * BT + b_in;

    const float  f   = features[b * T + t];
    const float4 w1v = w1[t];
    const float4 b1v = b1[t];
    const float4 b2v = b2[t];

    const float h0 = leaky(fmaf(f, w1v.x, b1v.x));
    const float h1 = leaky(fmaf(f, w1v.y, b1v.y));
    const float h2 = leaky(fmaf(f, w1v.z, b1v.z));
    const float h3 = leaky(fmaf(f, w1v.w, b1v.w));

    const float4 w20 = w2[t * 4 + 0];
    const float4 w21 = w2[t * 4 + 1];
    const float4 w22 = w2[t * 4 + 2];
    const float4 w23 = w2[t * 4 + 3];

    float4 o;
    o.x = leaky(fmaf(h3, w23.x, fmaf(h2, w22.x, fmaf(h1, w21.x, fmaf(h0, w20.x, b2v.x)))));
    o.y = leaky(fmaf(h3, w23.y, fmaf(h2, w22.y, fmaf(h1, w21.y, fmaf(h0, w20.y, b2v.y)))));
    o.z = leaky(fmaf(h3, w23.z, fmaf(h2, w22.z, fmaf(h1, w21.z, fmaf(h0, w20.z, b2v.z)))));
    o.w = leaky(fmaf(h3, w23.w, fmaf(h2, w22.w, fmaf(h1, w21.w, fmaf(h0, w20.w, b2v.w)))));

    const size_t base = ((size_t)(bt * T + t) * 2) * BT + b_in;
    g_h2h[base]      = __floats2half2_rn(o.x, o.y);
    g_h2h[base + BT] = __floats2half2_rn(o.z, o.w);
}

// ---------------------------------------------------------------------------
// Kernel B: out[b,g] = sum_e dot(h2[b, edge[g,e], :], w3[g,e,:]) + b3[g]
// Warp lanes = 32 batches (conflict-free LDS), each warp owns a 32-g tile.
// SMEM tile: [T][2][32] half2 = 128 KB per block.
// ---------------------------------------------------------------------------
__global__ void __launch_bounds__(NWARP * 32, 1)
gather_kernel(const int*   __restrict__ edge,
              const float* __restrict__ w3,
              const float* __restrict__ b3,
              float*       __restrict__ out) {
    extern __shared__ __half2 s_h2[];   // [T * 2 * BT]

    const int bt = blockIdx.y;

    // Stage the 128 KB tile: gmem layout == smem layout -> linear float4 copy.
    {
        const float4* src = reinterpret_cast<const float4*>(g_h2h + (size_t)bt * T * 2 * BT);
        float4*       dst = reinterpret_cast<float4*>(s_h2);
        const int n = T * 2 * BT / 4;   // 8192 float4
        for (int i = threadIdx.x; i < n; i += NWARP * 32) dst[i] = src[i];
    }
    __syncthreads();

    const int w     = threadIdx.x >> 5;
    const int lane  = threadIdx.x & 31;
    const int gbase = blockIdx.x * GPB + w * 32;
    if (gbase >= G) return;            // whole-tile granularity (G % 32 == 0)

    const int b = bt * BT + lane;
    float* orow = out + (size_t)b * G + gbase;

    #pragma unroll
    for (int chunk = 0; chunk < 4; chunk++) {
        float acc[8];
        #pragma unroll
        for (int gg = 0; gg < 8; gg++) {
            const int g = gbase + chunk * 8 + gg;

            const int e0 = __ldg(edge + 3 * g + 0);
            const int e1 = __ldg(edge + 3 * g + 1);
            const int e2 = __ldg(edge + 3 * g + 2);

            const float4* w3p = reinterpret_cast<const float4*>(w3 + (size_t)g * 12);
            const float4 wa = __ldg(w3p + 0);
            const float4 wb = __ldg(w3p + 1);
            const float4 wc = __ldg(w3p + 2);

            float r = __ldg(b3 + g);

            // edge 0
            {
                const float2 f0 = __half22float2(s_h2[(e0 * 2 + 0) * BT + lane]);
                const float2 f1 = __half22float2(s_h2[(e0 * 2 + 1) * BT + lane]);
                r = fmaf(f0.x, wa.x, r); r = fmaf(f0.y, wa.y, r);
                r = fmaf(f1.x, wa.z, r); r = fmaf(f1.y, wa.w, r);
            }
            // edge 1
            {
                const float2 f0 = __half22float2(s_h2[(e1 * 2 + 0) * BT + lane]);
                const float2 f1 = __half22float2(s_h2[(e1 * 2 + 1) * BT + lane]);
                r = fmaf(f0.x, wb.x, r); r = fmaf(f0.y, wb.y, r);
                r = fmaf(f1.x, wb.z, r); r = fmaf(f1.y, wb.w, r);
            }
            // edge 2
            {
                const float2 f0 = __half22float2(s_h2[(e2 * 2 + 0) * BT + lane]);
                const float2 f1 = __half22float2(s_h2[(e2 * 2 + 1) * BT + lane]);
                r = fmaf(f0.x, wc.x, r); r = fmaf(f0.y, wc.y, r);
                r = fmaf(f1.x, wc.z, r); r = fmaf(f1.y, wc.w, r);
            }
            acc[gg] = r;
        }
        // 2 coalesced float4 stores per lane (contiguous in g within the row)
        float4* op = reinterpret_cast<float4*>(orow + chunk * 8);
        op[0] = make_float4(acc[0], acc[1], acc[2], acc[3]);
        op[1] = make_float4(acc[4], acc[5], acc[6], acc[7]);
    }
}

extern "C" void kernel_launch(void* const* d_in, const int* in_sizes, int n_in,
                              void* d_out, int out_size) {
    const float* features = (const float*)d_in[0];   // [B, T]
    const float* w1       = (const float*)d_in[1];   // [T, K]
    const float* b1       = (const float*)d_in[2];   // [T, K]
    const float* w2       = (const float*)d_in[3];   // [T, K, K]
    const float* b2       = (const float*)d_in[4];   // [T, K]
    const float* w3       = (const float*)d_in[5];   // [G, EPG, K]
    const float* b3       = (const float*)d_in[6];   // [G]
    const int*   edge     = (const int*)  d_in[7];   // [G, EPG]
    float*       out      = (float*)d_out;           // [B, G]

    dim3 gridA(NBT, T / 16);
    dim3 blockA(BT, 16);
    h2_kernel<<<gridA, blockA>>>(features,
                                 (const float4*)w1, (const float4*)b1,
                                 (const float4*)w2, (const float4*)b2);

    const int smem = T * 2 * BT * sizeof(__half2);   // 128 KB
    cudaFuncSetAttribute(gather_kernel,
                         cudaFuncAttributeMaxDynamicSharedMemorySize, smem);
    dim3 gridB(NGB, NBT);
    gather_kernel<<<gridB, NWARP * 32, smem>>>(edge, w3, b3, out);
}

// round 3
// speedup vs baseline: 1.5841x; 1.5262x over previous
#include <cuda_runtime.h>
#include <cuda_fp16.h>
#include <cuda_pipeline.h>

#define T    512
#define K    4
#define G    20000
#define EPG  3
#define B    512

#define BT     32                  // batches per tile (= lanes)
#define NBT    (B / BT)            // 16
#define NWARP  16
#define BLKG   (NWARP * 32)        // 512 threads
#define GPB    512                 // g per block
#define NGB    40                  // 40*512 = 20480 >= 20000
#define GPAD   (NGB * GPB)         // 20480

// h2 fp16, layout [bt][t][b_in] as uint2 (k0k1, k2k3): 2 MB, L2-resident.
__device__ uint2  g_h2u[NBT * T * BT];
// per-g 64B records: q0={e0*32,e1*32,e2*32,b3}, q1..q3 = w3[12]
__device__ float4 g_grec[GPAD * 4];

__device__ __forceinline__ float leaky(float x) {
    return x > 0.0f ? x : 0.01f * x;
}

// ---------------------------------------------------------------------------
// Pack per-g records (edges pre-scaled to smem uint2 indices, + b3 + w3).
// ---------------------------------------------------------------------------
__global__ void pack_kernel(const int*   __restrict__ edge,
                            const float* __restrict__ w3,
                            const float* __restrict__ b3) {
    const int g = blockIdx.x * blockDim.x + threadIdx.x;
    if (g >= GPAD) return;
    float4 q0, q1, q2, q3;
    if (g < G) {
        const int e0 = edge[3 * g + 0];
        const int e1 = edge[3 * g + 1];
        const int e2 = edge[3 * g + 2];
        q0 = make_float4(__int_as_float(e0 * BT), __int_as_float(e1 * BT),
                         __int_as_float(e2 * BT), b3[g]);
        const float4* w3p = reinterpret_cast<const float4*>(w3 + (size_t)g * 12);
        q1 = w3p[0]; q2 = w3p[1]; q3 = w3p[2];
    } else {
        q0 = make_float4(0.f, 0.f, 0.f, 0.f);
        q1 = q0; q2 = q0; q3 = q0;
    }
    float4* r = g_grec + (size_t)g * 4;
    r[0] = q0; r[1] = q1; r[2] = q2; r[3] = q3;
}

// ---------------------------------------------------------------------------
// Kernel A: h2 -> fp16, layout [bt][t][b_in] uint2.
// ---------------------------------------------------------------------------
__global__ void h2_kernel(const float*  __restrict__ features,
                          const float4* __restrict__ w1,
                          const float4* __restrict__ b1,
                          const float4* __restrict__ w2,
                          const float4* __restrict__ b2) {
    const int b_in = threadIdx.x;
    const int t    = blockIdx.y * 16 + threadIdx.y;
    const int bt   = blockIdx.x;
    const int b    = bt * BT + b_in;

    const float  f   = features[b * T + t];
    const float4 w1v = w1[t];
    const float4 b1v = b1[t];
    const float4 b2v = b2[t];

    const float h0 = leaky(fmaf(f, w1v.x, b1v.x));
    const float h1 = leaky(fmaf(f, w1v.y, b1v.y));
    const float h2 = leaky(fmaf(f, w1v.z, b1v.z));
    const float h3 = leaky(fmaf(f, w1v.w, b1v.w));

    const float4 w20 = w2[t * 4 + 0];
    const float4 w21 = w2[t * 4 + 1];
    const float4 w22 = w2[t * 4 + 2];
    const float4 w23 = w2[t * 4 + 3];

    float4 o;
    o.x = leaky(fmaf(h3, w23.x, fmaf(h2, w22.x, fmaf(h1, w21.x, fmaf(h0, w20.x, b2v.x)))));
    o.y = leaky(fmaf(h3, w23.y, fmaf(h2, w22.y, fmaf(h1, w21.y, fmaf(h0, w20.y, b2v.y)))));
    o.z = leaky(fmaf(h3, w23.z, fmaf(h2, w22.z, fmaf(h1, w21.z, fmaf(h0, w20.z, b2v.z)))));
    o.w = leaky(fmaf(h3, w23.w, fmaf(h2, w22.w, fmaf(h1, w21.w, fmaf(h0, w20.w, b2v.w)))));

    const __half2 p0 = __floats2half2_rn(o.x, o.y);
    const __half2 p1 = __floats2half2_rn(o.z, o.w);
    uint2 p;
    p.x = *reinterpret_cast<const unsigned int*>(&p0);
    p.y = *reinterpret_cast<const unsigned int*>(&p1);
    g_h2u[((size_t)bt * T + t) * BT + b_in] = p;
}

// ---------------------------------------------------------------------------
// Gather kernel: everything staged in SMEM; SMEM output tile for coalescing.
// smem: h2 tile 128KB | records 32KB | out tile 64KB (xor-swizzled) = 224KB
// ---------------------------------------------------------------------------
__global__ void __launch_bounds__(BLKG, 1)
gather_kernel(float* __restrict__ out) {
    extern __shared__ char smem_raw[];
    uint2*  s_h2  = reinterpret_cast<uint2*>(smem_raw);                    // T*BT
    float4* s_rec = reinterpret_cast<float4*>(smem_raw + 131072);          // GPB*4
    float*  s_out = reinterpret_cast<float*>(smem_raw + 131072 + 32768);   // GPB*32

    const int tid  = threadIdx.x;
    const int bt   = blockIdx.y;
    const int gbase = blockIdx.x * GPB;

    // Stage h2 tile (8192 x 16B) + records (2048 x 16B) via cp.async.
    {
        const uint4* src = reinterpret_cast<const uint4*>(g_h2u + (size_t)bt * T * BT);
        uint4*       dst = reinterpret_cast<uint4*>(s_h2);
        #pragma unroll
        for (int i = tid; i < T * BT / 2; i += BLKG)
            __pipeline_memcpy_async(&dst[i], &src[i], 16);

        const float4* rsrc = g_grec + (size_t)gbase * 4;
        #pragma unroll
        for (int i = tid; i < GPB * 4; i += BLKG)
            __pipeline_memcpy_async(&s_rec[i], &rsrc[i], 16);
    }
    __pipeline_commit();
    __pipeline_wait_prior(0);
    __syncthreads();

    const int w    = tid >> 5;
    const int lane = tid & 31;

    // Compute: warp w owns g_local in [w*32, w*32+32); lane = batch.
    #pragma unroll 4
    for (int gg = 0; gg < 32; gg++) {
        const int gl = w * 32 + gg;

        const float4 q0 = s_rec[gl * 4 + 0];
        const float4 q1 = s_rec[gl * 4 + 1];
        const float4 q2 = s_rec[gl * 4 + 2];
        const float4 q3 = s_rec[gl * 4 + 3];

        const uint2 p0 = s_h2[__float_as_int(q0.x) + lane];
        const uint2 p1 = s_h2[__float_as_int(q0.y) + lane];
        const uint2 p2 = s_h2[__float_as_int(q0.z) + lane];

        float r = q0.w;
        {
            const float2 f0 = __half22float2(*reinterpret_cast<const __half2*>(&p0.x));
            const float2 f1 = __half22float2(*reinterpret_cast<const __half2*>(&p0.y));
            r = fmaf(f0.x, q1.x, r); r = fmaf(f0.y, q1.y, r);
            r = fmaf(f1.x, q1.z, r); r = fmaf(f1.y, q1.w, r);
        }
        {
            const float2 f0 = __half22float2(*reinterpret_cast<const __half2*>(&p1.x));
            const float2 f1 = __half22float2(*reinterpret_cast<const __half2*>(&p1.y));
            r = fmaf(f0.x, q2.x, r); r = fmaf(f0.y, q2.y, r);
            r = fmaf(f1.x, q2.z, r); r = fmaf(f1.y, q2.w, r);
        }
        {
            const float2 f0 = __half22float2(*reinterpret_cast<const __half2*>(&p2.x));
            const float2 f1 = __half22float2(*reinterpret_cast<const __half2*>(&p2.y));
            r = fmaf(f0.x, q3.x, r); r = fmaf(f0.y, q3.y, r);
            r = fmaf(f1.x, q3.z, r); r = fmaf(f1.y, q3.w, r);
        }
        // xor-swizzled SMEM store: conflict-free (lane ^ gg is a permutation)
        s_out[gl * 32 + (lane ^ gg)] = r;
    }
    __syncthreads();

    // Coalesced write-out: lane -> consecutive g, conflict-free swizzled reads.
    #pragma unroll
    for (int it = 0; it < 8; it++) {
        const int b_local = it * 4 + (tid >> 7);
        const int b       = bt * BT + b_local;
        const int gl0     = tid & 127;
        #pragma unroll
        for (int j = 0; j < 4; j++) {
            const int gl = gl0 + j * 128;
            const int g  = gbase + gl;
            if (g < G) {
                out[(size_t)b * G + g] = s_out[gl * 32 + (b_local ^ (gl & 31))];
            }
        }
    }
}

extern "C" void kernel_launch(void* const* d_in, const int* in_sizes, int n_in,
                              void* d_out, int out_size) {
    const float* features = (const float*)d_in[0];   // [B, T]
    const float* w1       = (const float*)d_in[1];   // [T, K]
    const float* b1       = (const float*)d_in[2];   // [T, K]
    const float* w2       = (const float*)d_in[3];   // [T, K, K]
    const float* b2       = (const float*)d_in[4];   // [T, K]
    const float* w3       = (const float*)d_in[5];   // [G, EPG, K]
    const float* b3       = (const float*)d_in[6];   // [G]
    const int*   edge     = (const int*)  d_in[7];   // [G, EPG]
    float*       out      = (float*)d_out;           // [B, G]

    pack_kernel<<<GPAD / 256, 256>>>(edge, w3, b3);

    dim3 gridA(NBT, T / 16);
    dim3 blockA(BT, 16);
    h2_kernel<<<gridA, blockA>>>(features,
                                 (const float4*)w1, (const float4*)b1,
                                 (const float4*)w2, (const float4*)b2);

    const int smem = 131072 + 32768 + 65536;   // 224 KB
    cudaFuncSetAttribute(gather_kernel,
                         cudaFuncAttributeMaxDynamicSharedMemorySize, smem);
    dim3 gridB(NGB, NBT);
    gather_kernel<<<gridB, BLKG, smem>>>(out);
}

// round 4
// speedup vs baseline: 1.8596x; 1.1739x over previous
#include <cuda_runtime.h>
#include <cuda_fp16.h>
#include <cuda_pipeline.h>

#define T    512
#define K    4
#define G    20000
#define EPG  3
#define B    512

#define BT     32                  // batches per tile (= lanes)
#define NBT    (B / BT)            // 16
#define NWARP  16
#define BLKG   (NWARP * 32)        // 512 threads
#define GPB    256                 // g per chunk
#define NCHUNK 79                  // 79*256 = 20224 >= 20000
#define GPAD   (NCHUNK * GPB)      // 20224
#define NSPLIT 9                   // gather blocks per bt: 16*9 = 144 ~= 1 wave

// h2 fp16, layout [bt][t][b_in] as uint2 (k0k1, k2k3): 2 MB, L2-resident.
__device__ uint2  g_h2u[NBT * T * BT];
// per-g 64B records: q0={e0*32,e1*32,e2*32,b3}, q1..q3 = w3[12]
__device__ float4 g_grec[GPAD * 4];

__device__ __forceinline__ float leaky(float x) {
    return x > 0.0f ? x : 0.01f * x;
}

// ---------------------------------------------------------------------------
// Fused prep kernel. Blocks [0, 512): h2 compute. Blocks [512, 512+158): pack.
// ---------------------------------------------------------------------------
#define H2_BLOCKS   512
#define PACK_ITEMS  (GPAD * 4)                         // 80896 record quarters
#define PACK_BLOCKS ((PACK_ITEMS + BLKG - 1) / BLKG)   // 158

__global__ void prep_kernel(const float*  __restrict__ features,
                            const float4* __restrict__ w1,
                            const float4* __restrict__ b1,
                            const float4* __restrict__ w2,
                            const float4* __restrict__ b2,
                            const int*    __restrict__ edge,
                            const float*  __restrict__ w3,
                            const float*  __restrict__ b3) {
    const int tid = threadIdx.x;
    if (blockIdx.x < H2_BLOCKS) {
        // ----- h2 role: block = (bt, t-chunk of 16) -----
        const int b_in = tid & 31;
        const int ty   = tid >> 5;
        const int bt   = blockIdx.x & (NBT - 1);
        const int t    = (blockIdx.x >> 4) * 16 + ty;
        const int b    = bt * BT + b_in;

        const float  f   = features[b * T + t];
        const float4 w1v = w1[t];
        const float4 b1v = b1[t];
        const float4 b2v = b2[t];

        const float h0 = leaky(fmaf(f, w1v.x, b1v.x));
        const float h1 = leaky(fmaf(f, w1v.y, b1v.y));
        const float h2 = leaky(fmaf(f, w1v.z, b1v.z));
        const float h3 = leaky(fmaf(f, w1v.w, b1v.w));

        const float4 w20 = w2[t * 4 + 0];
        const float4 w21 = w2[t * 4 + 1];
        const float4 w22 = w2[t * 4 + 2];
        const float4 w23 = w2[t * 4 + 3];

        float4 o;
        o.x = leaky(fmaf(h3, w23.x, fmaf(h2, w22.x, fmaf(h1, w21.x, fmaf(h0, w20.x, b2v.x)))));
        o.y = leaky(fmaf(h3, w23.y, fmaf(h2, w22.y, fmaf(h1, w21.y, fmaf(h0, w20.y, b2v.y)))));
        o.z = leaky(fmaf(h3, w23.z, fmaf(h2, w22.z, fmaf(h1, w21.z, fmaf(h0, w20.z, b2v.z)))));
        o.w = leaky(fmaf(h3, w23.w, fmaf(h2, w22.w, fmaf(h1, w21.w, fmaf(h0, w20.w, b2v.w)))));

        const __half2 p0 = __floats2half2_rn(o.x, o.y);
        const __half2 p1 = __floats2half2_rn(o.z, o.w);
        uint2 p;
        p.x = *reinterpret_cast<const unsigned int*>(&p0);
        p.y = *reinterpret_cast<const unsigned int*>(&p1);
        g_h2u[((size_t)bt * T + t) * BT + b_in] = p;
    } else {
        // ----- pack role: one thread per 16B record quarter -----
        const int i = (blockIdx.x - H2_BLOCKS) * BLKG + tid;
        if (i >= PACK_ITEMS) return;
        const int g    = i >> 2;
        const int part = i & 3;
        float4 q = make_float4(0.f, 0.f, 0.f, 0.f);
        if (g < G) {
            if (part == 0) {
                q = make_float4(__int_as_float(edge[3 * g + 0] * BT),
                                __int_as_float(edge[3 * g + 1] * BT),
                                __int_as_float(edge[3 * g + 2] * BT),
                                b3[g]);
            } else {
                q = reinterpret_cast<const float4*>(w3)[g * 3 + part - 1];
            }
        }
        g_grec[i] = q;
    }
}

// ---------------------------------------------------------------------------
// Gather: persistent h2 tile + double-buffered record chunks + smem out tile.
// smem: h2 128KB | rec 2x16KB | out 32KB = 192KB
// ---------------------------------------------------------------------------
#define SM_H2   0
#define SM_REC  131072
#define SM_OUT  (131072 + 32768)

__global__ void __launch_bounds__(BLKG, 1)
gather_kernel(float* __restrict__ out) {
    extern __shared__ char smem_raw[];
    uint2*  s_h2  = reinterpret_cast<uint2*>(smem_raw + SM_H2);    // [T*BT]
    float4* s_rec = reinterpret_cast<float4*>(smem_raw + SM_REC);  // [2][GPB*4]
    float*  s_out = reinterpret_cast<float*>(smem_raw + SM_OUT);   // [GPB*32]

    const int tid  = threadIdx.x;
    const int bt   = blockIdx.y;
    const int w    = tid >> 5;
    const int lane = tid & 31;

    // Stage persistent h2 tile (8192 x 16B) + first record chunk.
    {
        const uint4* src = reinterpret_cast<const uint4*>(g_h2u + (size_t)bt * T * BT);
        uint4*       dst = reinterpret_cast<uint4*>(s_h2);
        #pragma unroll
        for (int i = tid; i < T * BT / 2; i += BLKG)
            __pipeline_memcpy_async(&dst[i], &src[i], 16);
    }
    int c = blockIdx.x;   // first chunk for this split
    {
        const float4* rsrc = g_grec + (size_t)c * GPB * 4;
        #pragma unroll
        for (int i = tid; i < GPB * 4; i += BLKG)
            __pipeline_memcpy_async(&s_rec[i], &rsrc[i], 16);
    }
    __pipeline_commit();
    __pipeline_wait_prior(0);
    __syncthreads();

    int buf = 0;
    while (true) {
        const int  cn       = c + NSPLIT;
        const bool has_next = (cn < NCHUNK);

        // Prefetch next record chunk into the other buffer (hidden by compute).
        if (has_next) {
            const float4* rsrc = g_grec + (size_t)cn * GPB * 4;
            float4*       rdst = s_rec + (buf ^ 1) * GPB * 4;
            #pragma unroll
            for (int i = tid; i < GPB * 4; i += BLKG)
                __pipeline_memcpy_async(&rdst[i], &rsrc[i], 16);
            __pipeline_commit();
        }

        // Compute this chunk: warp w owns g_local in [w*16, w*16+16).
        const float4* rec = s_rec + buf * GPB * 4;
        #pragma unroll 4
        for (int gg = 0; gg < 16; gg++) {
            const int gl = w * 16 + gg;

            const float4 q0 = rec[gl * 4 + 0];
            const float4 q1 = rec[gl * 4 + 1];
            const float4 q2 = rec[gl * 4 + 2];
            const float4 q3 = rec[gl * 4 + 3];

            const uint2 p0 = s_h2[__float_as_int(q0.x) + lane];
            const uint2 p1 = s_h2[__float_as_int(q0.y) + lane];
            const uint2 p2 = s_h2[__float_as_int(q0.z) + lane];

            float r = q0.w;
            {
                const float2 f0 = __half22float2(*reinterpret_cast<const __half2*>(&p0.x));
                const float2 f1 = __half22float2(*reinterpret_cast<const __half2*>(&p0.y));
                r = fmaf(f0.x, q1.x, r); r = fmaf(f0.y, q1.y, r);
                r = fmaf(f1.x, q1.z, r); r = fmaf(f1.y, q1.w, r);
            }
            {
                const float2 f0 = __half22float2(*reinterpret_cast<const __half2*>(&p1.x));
                const float2 f1 = __half22float2(*reinterpret_cast<const __half2*>(&p1.y));
                r = fmaf(f0.x, q2.x, r); r = fmaf(f0.y, q2.y, r);
                r = fmaf(f1.x, q2.z, r); r = fmaf(f1.y, q2.w, r);
            }
            {
                const float2 f0 = __half22float2(*reinterpret_cast<const __half2*>(&p2.x));
                const float2 f1 = __half22float2(*reinterpret_cast<const __half2*>(&p2.y));
                r = fmaf(f0.x, q3.x, r); r = fmaf(f0.y, q3.y, r);
                r = fmaf(f1.x, q3.z, r); r = fmaf(f1.y, q3.w, r);
            }
            // xor-swizzled, conflict-free
            s_out[gl * 32 + (lane ^ (gl & 31))] = r;
        }
        __syncthreads();

        // Coalesced write-out of this chunk (GPB*32 floats).
        {
            const int gbase   = c * GPB;
            const int b_sub   = tid >> 7;        // 0..3
            const int lane128 = tid & 127;
            #pragma unroll
            for (int it = 0; it < 8; it++) {
                const int b_local = it * 4 + b_sub;
                const int b       = bt * BT + b_local;
                #pragma unroll
                for (int j = 0; j < 2; j++) {
                    const int gl = lane128 + j * 128;
                    const int g  = gbase + gl;
                    if (g < G)
                        out[(size_t)b * G + g] = s_out[gl * 32 + (b_local ^ (gl & 31))];
                }
            }
        }

        if (!has_next) break;
        __pipeline_wait_prior(0);
        __syncthreads();   // next rec visible; s_out free to overwrite
        buf ^= 1;
        c = cn;
    }
}

extern "C" void kernel_launch(void* const* d_in, const int* in_sizes, int n_in,
                              void* d_out, int out_size) {
    const float* features = (const float*)d_in[0];   // [B, T]
    const float* w1       = (const float*)d_in[1];   // [T, K]
    const float* b1       = (const float*)d_in[2];   // [T, K]
    const float* w2       = (const float*)d_in[3];   // [T, K, K]
    const float* b2       = (const float*)d_in[4];   // [T, K]
    const float* w3       = (const float*)d_in[5];   // [G, EPG, K]
    const float* b3       = (const float*)d_in[6];   // [G]
    const int*   edge     = (const int*)  d_in[7];   // [G, EPG]
    float*       out      = (float*)d_out;           // [B, G]

    prep_kernel<<<H2_BLOCKS + PACK_BLOCKS, BLKG>>>(
        features, (const float4*)w1, (const float4*)b1,
        (const float4*)w2, (const float4*)b2, edge, w3, b3);

    const int smem = 131072 + 32768 + 32768;   // 192 KB
    cudaFuncSetAttribute(gather_kernel,
                         cudaFuncAttributeMaxDynamicSharedMemorySize, smem);
    dim3 gridB(NSPLIT, NBT);
    gather_kernel<<<gridB, BLKG, smem>>>(out);
}

// round 5
// speedup vs baseline: 1.9778x; 1.0636x over previous
#include <cuda_runtime.h>
#include <cuda_fp16.h>
#include <cuda_pipeline.h>

#define T    512
#define K    4
#define G    20000
#define EPG  3
#define B    512

#define BT     32                  // batches per tile (= lanes)
#define NBT    (B / BT)            // 16
#define BLKG   1024                // gather threads: 32 warps
#define NWARP  (BLKG / 32)
#define GPB    256                 // g per chunk
#define NCHUNK 79                  // 79*256 = 20224 >= 20000
#define GPAD   (NCHUNK * GPB)      // 20224
#define NSPLIT 9                   // gather blocks per bt: 16*9 = 144 ~= 1 wave
#define BLKP   512                 // prep threads

// h2 fp16, layout [bt][t][b_in] as uint2 (k0k1, k2k3): 2 MB, L2-resident.
__device__ uint2  g_h2u[NBT * T * BT];
// per-g 64B records: q0={e0*32,e1*32,e2*32,b3}, q1..q3 = w3[12]
__device__ float4 g_grec[GPAD * 4];

__device__ __forceinline__ float leaky(float x) {
    return x > 0.0f ? x : 0.01f * x;
}

// Packed f32x2 FMA (Blackwell FFMA2) — bit-identical to two scalar fp32 FMAs.
__device__ __forceinline__ float2 ffma2(float2 a, float2 b, float2 c) {
    float2 d;
    asm("{\n\t"
        ".reg .b64 ra, rb, rc, rd;\n\t"
        "mov.b64 ra, {%2, %3};\n\t"
        "mov.b64 rb, {%4, %5};\n\t"
        "mov.b64 rc, {%6, %7};\n\t"
        "fma.rn.f32x2 rd, ra, rb, rc;\n\t"
        "mov.b64 {%0, %1}, rd;\n\t"
        "}"
        : "=f"(d.x), "=f"(d.y)
        : "f"(a.x), "f"(a.y), "f"(b.x), "f"(b.y), "f"(c.x), "f"(c.y));
    return d;
}

// ---------------------------------------------------------------------------
// Fused prep kernel. Blocks [0, 512): h2 compute. Blocks [512, 512+158): pack.
// ---------------------------------------------------------------------------
#define H2_BLOCKS   512
#define PACK_ITEMS  (GPAD * 4)                         // 80896 record quarters
#define PACK_BLOCKS ((PACK_ITEMS + BLKP - 1) / BLKP)   // 158

__global__ void prep_kernel(const float*  __restrict__ features,
                            const float4* __restrict__ w1,
                            const float4* __restrict__ b1,
                            const float4* __restrict__ w2,
                            const float4* __restrict__ b2,
                            const int*    __restrict__ edge,
                            const float*  __restrict__ w3,
                            const float*  __restrict__ b3) {
    const int tid = threadIdx.x;
    if (blockIdx.x < H2_BLOCKS) {
        const int b_in = tid & 31;
        const int ty   = tid >> 5;
        const int bt   = blockIdx.x & (NBT - 1);
        const int t    = (blockIdx.x >> 4) * 16 + ty;
        const int b    = bt * BT + b_in;

        const float  f   = features[b * T + t];
        const float4 w1v = w1[t];
        const float4 b1v = b1[t];
        const float4 b2v = b2[t];

        const float h0 = leaky(fmaf(f, w1v.x, b1v.x));
        const float h1 = leaky(fmaf(f, w1v.y, b1v.y));
        const float h2 = leaky(fmaf(f, w1v.z, b1v.z));
        const float h3 = leaky(fmaf(f, w1v.w, b1v.w));

        const float4 w20 = w2[t * 4 + 0];
        const float4 w21 = w2[t * 4 + 1];
        const float4 w22 = w2[t * 4 + 2];
        const float4 w23 = w2[t * 4 + 3];

        float4 o;
        o.x = leaky(fmaf(h3, w23.x, fmaf(h2, w22.x, fmaf(h1, w21.x, fmaf(h0, w20.x, b2v.x)))));
        o.y = leaky(fmaf(h3, w23.y, fmaf(h2, w22.y, fmaf(h1, w21.y, fmaf(h0, w20.y, b2v.y)))));
        o.z = leaky(fmaf(h3, w23.z, fmaf(h2, w22.z, fmaf(h1, w21.z, fmaf(h0, w20.z, b2v.z)))));
        o.w = leaky(fmaf(h3, w23.w, fmaf(h2, w22.w, fmaf(h1, w21.w, fmaf(h0, w20.w, b2v.w)))));

        const __half2 p0 = __floats2half2_rn(o.x, o.y);
        const __half2 p1 = __floats2half2_rn(o.z, o.w);
        uint2 p;
        p.x = *reinterpret_cast<const unsigned int*>(&p0);
        p.y = *reinterpret_cast<const unsigned int*>(&p1);
        g_h2u[((size_t)bt * T + t) * BT + b_in] = p;
    } else {
        const int i = (blockIdx.x - H2_BLOCKS) * BLKP + tid;
        if (i >= PACK_ITEMS) return;
        const int g    = i >> 2;
        const int part = i & 3;
        float4 q = make_float4(0.f, 0.f, 0.f, 0.f);
        if (g < G) {
            if (part == 0) {
                q = make_float4(__int_as_float(edge[3 * g + 0] * BT),
                                __int_as_float(edge[3 * g + 1] * BT),
                                __int_as_float(edge[3 * g + 2] * BT),
                                b3[g]);
            } else {
                q = reinterpret_cast<const float4*>(w3)[g * 3 + part - 1];
            }
        }
        g_grec[i] = q;
    }
}

// ---------------------------------------------------------------------------
// Gather: persistent h2 tile + double-buffered record chunks + smem out tile.
// smem: h2 128KB | rec 2x16KB | out 32KB = 192KB, 1024 threads (occ 50%).
// ---------------------------------------------------------------------------
#define SM_H2   0
#define SM_REC  131072
#define SM_OUT  (131072 + 32768)

__global__ void __launch_bounds__(BLKG, 1)
gather_kernel(float* __restrict__ out) {
    extern __shared__ char smem_raw[];
    uint2*  s_h2  = reinterpret_cast<uint2*>(smem_raw + SM_H2);    // [T*BT]
    float4* s_rec = reinterpret_cast<float4*>(smem_raw + SM_REC);  // [2][GPB*4]
    float*  s_out = reinterpret_cast<float*>(smem_raw + SM_OUT);   // [GPB*32]

    const int tid  = threadIdx.x;
    const int bt   = blockIdx.y;
    const int w    = tid >> 5;
    const int lane = tid & 31;

    // Stage persistent h2 tile (8192 x 16B) + first record chunk.
    {
        const uint4* src = reinterpret_cast<const uint4*>(g_h2u + (size_t)bt * T * BT);
        uint4*       dst = reinterpret_cast<uint4*>(s_h2);
        #pragma unroll
        for (int i = tid; i < T * BT / 2; i += BLKG)
            __pipeline_memcpy_async(&dst[i], &src[i], 16);
    }
    int c = blockIdx.x;   // first chunk for this split
    {
        const float4* rsrc = g_grec + (size_t)c * GPB * 4;
        #pragma unroll
        for (int i = tid; i < GPB * 4; i += BLKG)
            __pipeline_memcpy_async(&s_rec[i], &rsrc[i], 16);
    }
    __pipeline_commit();
    __pipeline_wait_prior(0);
    __syncthreads();

    const uint2* s_h2_lane = s_h2 + lane;

    int buf = 0;
    while (true) {
        const int  cn       = c + NSPLIT;
        const bool has_next = (cn < NCHUNK);

        if (has_next) {
            const float4* rsrc = g_grec + (size_t)cn * GPB * 4;
            float4*       rdst = s_rec + (buf ^ 1) * GPB * 4;
            #pragma unroll
            for (int i = tid; i < GPB * 4; i += BLKG)
                __pipeline_memcpy_async(&rdst[i], &rsrc[i], 16);
            __pipeline_commit();
        }

        // Compute: warp w owns g_local in [w*8, w*8+8); lane = batch.
        const float4* rec = s_rec + buf * GPB * 4;
        #pragma unroll
        for (int gg = 0; gg < 8; gg++) {
            const int gl = w * 8 + gg;

            const float4 q0 = rec[gl * 4 + 0];
            const float4 q1 = rec[gl * 4 + 1];
            const float4 q2 = rec[gl * 4 + 2];
            const float4 q3 = rec[gl * 4 + 3];

            const uint2 p0 = s_h2_lane[__float_as_int(q0.x)];
            const uint2 p1 = s_h2_lane[__float_as_int(q0.y)];
            const uint2 p2 = s_h2_lane[__float_as_int(q0.z)];

            // Two interleaved f32x2 accumulator chains.
            float2 acc0 = make_float2(q0.w, 0.f);
            float2 acc1 = make_float2(0.f, 0.f);

            acc0 = ffma2(__half22float2(*reinterpret_cast<const __half2*>(&p0.x)),
                         make_float2(q1.x, q1.y), acc0);
            acc1 = ffma2(__half22float2(*reinterpret_cast<const __half2*>(&p0.y)),
                         make_float2(q1.z, q1.w), acc1);
            acc0 = ffma2(__half22float2(*reinterpret_cast<const __half2*>(&p1.x)),
                         make_float2(q2.x, q2.y), acc0);
            acc1 = ffma2(__half22float2(*reinterpret_cast<const __half2*>(&p1.y)),
                         make_float2(q2.z, q2.w), acc1);
            acc0 = ffma2(__half22float2(*reinterpret_cast<const __half2*>(&p2.x)),
                         make_float2(q3.x, q3.y), acc0);
            acc1 = ffma2(__half22float2(*reinterpret_cast<const __half2*>(&p2.y)),
                         make_float2(q3.z, q3.w), acc1);

            const float r = (acc0.x + acc1.x) + (acc0.y + acc1.y);

            s_out[gl * 32 + (lane ^ (gl & 31))] = r;   // conflict-free swizzle
        }
        __syncthreads();

        // Coalesced write-out: warp = batch row, lane = consecutive g.
        {
            const int gbase = c * GPB;
            float* orow = out + (size_t)(bt * BT + w) * G + gbase;
            #pragma unroll
            for (int it = 0; it < 8; it++) {
                const int gl = it * 32 + lane;
                if (gbase + gl < G)
                    orow[gl] = s_out[gl * 32 + (w ^ lane)];
            }
        }

        if (!has_next) break;
        __pipeline_wait_prior(0);
        __syncthreads();
        buf ^= 1;
        c = cn;
    }
}

extern "C" void kernel_launch(void* const* d_in, const int* in_sizes, int n_in,
                              void* d_out, int out_size) {
    const float* features = (const float*)d_in[0];   // [B, T]
    const float* w1       = (const float*)d_in[1];   // [T, K]
    const float* b1       = (const float*)d_in[2];   // [T, K]
    const float* w2       = (const float*)d_in[3];   // [T, K, K]
    const float* b2       = (const float*)d_in[4];   // [T, K]
    const float* w3       = (const float*)d_in[5];   // [G, EPG, K]
    const float* b3       = (const float*)d_in[6];   // [G]
    const int*   edge     = (const int*)  d_in[7];   // [G, EPG]
    float*       out      = (float*)d_out;           // [B, G]

    prep_kernel<<<H2_BLOCKS + PACK_BLOCKS, BLKP>>>(
        features, (const float4*)w1, (const float4*)b1,
        (const float4*)w2, (const float4*)b2, edge, w3, b3);

    const int smem = 131072 + 32768 + 32768;   // 192 KB
    cudaFuncSetAttribute(gather_kernel,
                         cudaFuncAttributeMaxDynamicSharedMemorySize, smem);
    dim3 gridB(NSPLIT, NBT);
    gather_kernel<<<gridB, BLKG, smem>>>(out);
}